// round 2
// baseline (speedup 1.0000x reference)
#include <cuda_runtime.h>
#include <cstdint>

// yoloLoss: preds (B,14,14,30) f32, truths (B,14,14,30) f32 -> scalar f32.
// Pure HBM-streaming reduction: 192.6 MB read, ~28us DRAM floor on GB300.

#define GRIDN   14
#define BOXN    2
#define LABELN  20
#define ALL_BOX 10          // 5*BOXN
#define CVALS   30          // ALL_BOX + LABELN
#define BATCH_INV (1.0f / 4096.0f)

#define CELLS_PER_BLOCK 128
#define FLOATS_PER_BLOCK (CELLS_PER_BLOCK * CVALS)   // 3840
#define F2_PER_BLOCK (FLOATS_PER_BLOCK / 2)          // 1920 (= 128 * 15 exactly)

__global__ void __launch_bounds__(CELLS_PER_BLOCK)
yolo_loss_kernel(const float* __restrict__ preds,
                 const float* __restrict__ truths,
                 float* __restrict__ out,
                 int n_cells, float batch_inv)
{
    __shared__ float sp[FLOATS_PER_BLOCK];
    __shared__ float st[FLOATS_PER_BLOCK];

    const int tid = threadIdx.x;
    const long long cell_base = (long long)blockIdx.x * CELLS_PER_BLOCK;
    const int count = min(CELLS_PER_BLOCK, n_cells - (int)cell_base);
    const long long fbase = cell_base * CVALS;

    // --- Coalesced staging: global -> shared ---
    if (count == CELLS_PER_BLOCK) {
        // 1920 float2 per tensor = 15 exact iterations of 128 threads
        const float2* gp = reinterpret_cast<const float2*>(preds + fbase);
        const float2* gt = reinterpret_cast<const float2*>(truths + fbase);
        float2* s2p = reinterpret_cast<float2*>(sp);
        float2* s2t = reinterpret_cast<float2*>(st);
        #pragma unroll
        for (int i = 0; i < F2_PER_BLOCK; i += CELLS_PER_BLOCK) {
            s2p[i + tid] = gp[i + tid];
            s2t[i + tid] = gt[i + tid];
        }
    } else {
        const int nf = count * CVALS;
        for (int i = tid; i < nf; i += CELLS_PER_BLOCK) {
            sp[i] = preds[fbase + i];
            st[i] = truths[fbase + i];
        }
    }
    __syncthreads();

    float contrib = 0.0f;
    if (tid < count) {
        const float* P = sp + tid * CVALS;
        const float* T = st + tid * CVALS;

        const float conf0 = P[4];
        const float conf1 = P[9];
        const float tconf = T[4];

        if (tconf > 0.0f) {
            const float CELLF = 1.0f / 14.0f;
            // truth box
            const float tcx = CELLF * T[0];
            const float tcy = CELLF * T[1];
            const float thw = 0.5f * T[2];
            const float thh = 0.5f * T[3];
            const float t_lt_x = tcx - thw, t_rb_x = tcx + thw;
            const float t_lt_y = tcy - thh, t_rb_y = tcy + thh;
            const float ta = (t_rb_x - t_lt_x) * (t_rb_y - t_lt_y);

            float iou[BOXN];
            #pragma unroll
            for (int b = 0; b < BOXN; b++) {
                const float* pb = P + 5 * b;
                const float pcx = CELLF * pb[0];
                const float pcy = CELLF * pb[1];
                const float phw = 0.5f * pb[2];
                const float phh = 0.5f * pb[3];
                const float p_lt_x = pcx - phw, p_rb_x = pcx + phw;
                const float p_lt_y = pcy - phh, p_rb_y = pcy + phh;
                const float lt_x = fmaxf(p_lt_x, t_lt_x);
                const float lt_y = fmaxf(p_lt_y, t_lt_y);
                const float rb_x = fminf(p_rb_x, t_rb_x);
                const float rb_y = fminf(p_rb_y, t_rb_y);
                const float wx = fmaxf(rb_x - lt_x, 0.0f);
                const float wy = fmaxf(rb_y - lt_y, 0.0f);
                const float inter = wx * wy;
                const float pa = (p_rb_x - p_lt_x) * (p_rb_y - p_lt_y);
                iou[b] = inter / (pa + ta - inter);
            }

            // responsible-box selection matching jnp argmax-first-index semantics
            int resp;
            if (iou[0] == iou[1]) {
                resp = (conf1 > conf0) ? 1 : 0;   // argmax of conf, first on tie
            } else {
                resp = (iou[1] > iou[0]) ? 1 : 0; // argmax of iou
            }
            const float max_iou = fmaxf(iou[0], iou[1]);

            const float* pr = P + 5 * resp;
            const float other_conf = (resp == 0) ? conf1 : conf0;

            // coordinate + size losses (COORD_RATE = 5)
            const float dx = pr[0] - T[0];
            const float dy = pr[1] - T[1];
            const float dw = sqrtf(pr[2]) - sqrtf(T[2]);
            const float dh = sqrtf(pr[3]) - sqrtf(T[3]);
            float c = 5.0f * (dx * dx + dy * dy + dw * dw + dh * dh);

            // responsible confidence loss
            const float dc = pr[4] - max_iou;
            c += dc * dc;

            // non-responsible confidence loss (NOOBJ_RATE = 0.5)
            c += 0.5f * other_conf * other_conf;

            // label loss
            #pragma unroll
            for (int k = 0; k < LABELN; k++) {
                const float d = P[ALL_BOX + k] - T[ALL_BOX + k];
                c += d * d;
            }
            contrib = c;
        } else {
            // no-object: 0.5 * (conf0^2 + conf1^2)
            contrib = 0.5f * (conf0 * conf0 + conf1 * conf1);
        }
    }

    // --- block reduction ---
    #pragma unroll
    for (int off = 16; off > 0; off >>= 1)
        contrib += __shfl_down_sync(0xFFFFFFFFu, contrib, off);

    __shared__ float warp_sums[CELLS_PER_BLOCK / 32];
    const int warp = tid >> 5;
    const int lane = tid & 31;
    if (lane == 0) warp_sums[warp] = contrib;
    __syncthreads();

    if (tid == 0) {
        float s = 0.0f;
        #pragma unroll
        for (int w = 0; w < CELLS_PER_BLOCK / 32; w++) s += warp_sums[w];
        atomicAdd(out, s * batch_inv);
    }
}

extern "C" void kernel_launch(void* const* d_in, const int* in_sizes, int n_in,
                              void* d_out, int out_size)
{
    const float* preds  = (const float*)d_in[0];
    const float* truths = (const float*)d_in[1];
    float* out = (float*)d_out;

    const int n_cells = in_sizes[0] / CVALS;   // 4096*14*14 = 802816
    const int blocks = (n_cells + CELLS_PER_BLOCK - 1) / CELLS_PER_BLOCK;

    // out is poisoned before timing; zero it inside the graph each replay
    cudaMemsetAsync(d_out, 0, sizeof(float), 0);
    yolo_loss_kernel<<<blocks, CELLS_PER_BLOCK, 0, 0>>>(preds, truths, out,
                                                        n_cells, BATCH_INV);
}

// round 3
// speedup vs baseline: 1.0919x; 1.0919x over previous
#include <cuda_runtime.h>
#include <cstdint>

// yoloLoss: preds (B,14,14,30) f32, truths (B,14,14,30) f32 -> scalar f32.
// Persistent-CTA, 2-stage cp.async double-buffered streaming reduction.
// 192.6 MB read, ~28us DRAM floor on GB300.

#define BOXN    2
#define LABELN  20
#define ALL_BOX 10
#define CVALS   30
#define BATCH_INV (1.0f / 4096.0f)

#define TILE    128                       // cells per tile
#define TFLOATS (TILE * CVALS)            // 3840 floats per tensor per tile
#define CHUNKS  (TFLOATS / 4)             // 960 16B chunks per tensor
#define STAGE_FLOATS (2 * TFLOATS)        // preds + truths per stage = 7680
#define NSTAGES 2
#define SMEM_BYTES (NSTAGES * STAGE_FLOATS * 4)   // 61440
#define NBLOCKS 444                        // 3 CTAs x 148 SMs

__device__ __forceinline__ void cp16(uint32_t dst, const float* src) {
    asm volatile("cp.async.cg.shared.global [%0], [%1], 16;" :: "r"(dst), "l"(src));
}
__device__ __forceinline__ void cp_commit() {
    asm volatile("cp.async.commit_group;");
}
__device__ __forceinline__ void cp_wait1() {
    asm volatile("cp.async.wait_group 1;");
}

// loss contribution of one cell given pointers to its 30 pred / 30 truth floats
__device__ __forceinline__ float cell_loss(const float* __restrict__ P,
                                           const float* __restrict__ T)
{
    const float conf0 = P[4];
    const float conf1 = P[9];
    const float tconf = T[4];

    if (tconf > 0.0f) {
        const float CELLF = 1.0f / 14.0f;
        const float tcx = CELLF * T[0];
        const float tcy = CELLF * T[1];
        const float thw = 0.5f * T[2];
        const float thh = 0.5f * T[3];
        const float t_lt_x = tcx - thw, t_rb_x = tcx + thw;
        const float t_lt_y = tcy - thh, t_rb_y = tcy + thh;
        const float ta = (t_rb_x - t_lt_x) * (t_rb_y - t_lt_y);

        float iou[BOXN];
        #pragma unroll
        for (int b = 0; b < BOXN; b++) {
            const float* pb = P + 5 * b;
            const float pcx = CELLF * pb[0];
            const float pcy = CELLF * pb[1];
            const float phw = 0.5f * pb[2];
            const float phh = 0.5f * pb[3];
            const float p_lt_x = pcx - phw, p_rb_x = pcx + phw;
            const float p_lt_y = pcy - phh, p_rb_y = pcy + phh;
            const float lt_x = fmaxf(p_lt_x, t_lt_x);
            const float lt_y = fmaxf(p_lt_y, t_lt_y);
            const float rb_x = fminf(p_rb_x, t_rb_x);
            const float rb_y = fminf(p_rb_y, t_rb_y);
            const float wx = fmaxf(rb_x - lt_x, 0.0f);
            const float wy = fmaxf(rb_y - lt_y, 0.0f);
            const float inter = wx * wy;
            const float pa = (p_rb_x - p_lt_x) * (p_rb_y - p_lt_y);
            iou[b] = inter / (pa + ta - inter);
        }

        // responsible box: jnp argmax-first-index tie semantics
        int resp;
        if (iou[0] == iou[1]) resp = (conf1 > conf0) ? 1 : 0;
        else                  resp = (iou[1] > iou[0]) ? 1 : 0;
        const float max_iou = fmaxf(iou[0], iou[1]);

        const float* pr = P + 5 * resp;
        const float other_conf = (resp == 0) ? conf1 : conf0;

        const float dx = pr[0] - T[0];
        const float dy = pr[1] - T[1];
        const float dw = sqrtf(pr[2]) - sqrtf(T[2]);
        const float dh = sqrtf(pr[3]) - sqrtf(T[3]);
        float c = 5.0f * (dx * dx + dy * dy + dw * dw + dh * dh);

        const float dc = pr[4] - max_iou;
        c += dc * dc;
        c += 0.5f * other_conf * other_conf;

        #pragma unroll
        for (int k = 0; k < LABELN; k++) {
            const float d = P[ALL_BOX + k] - T[ALL_BOX + k];
            c += d * d;
        }
        return c;
    } else {
        return 0.5f * (conf0 * conf0 + conf1 * conf1);
    }
}

__device__ __forceinline__ void prefetch_tile(int tile, int stage,
                                              const float* __restrict__ preds,
                                              const float* __restrict__ truths,
                                              uint32_t sbase, int tid)
{
    const long long base = (long long)tile * TFLOATS;
    const float* gp = preds + base;
    const float* gt = truths + base;
    const uint32_t s = sbase + (uint32_t)stage * (STAGE_FLOATS * 4);
    // 1920 16B chunks / 128 threads = 15 per thread
    #pragma unroll
    for (int k = 0; k < 15; k++) {
        const int idx = k * TILE + tid;          // 0..1919
        if (idx < CHUNKS) {
            cp16(s + idx * 16, gp + idx * 4);
        } else {
            const int j = idx - CHUNKS;
            cp16(s + TFLOATS * 4 + j * 16, gt + j * 4);
        }
    }
}

extern __shared__ float smem[];

__global__ void __launch_bounds__(TILE)
yolo_loss_kernel(const float* __restrict__ preds,
                 const float* __restrict__ truths,
                 float* __restrict__ out,
                 int n_tiles, int n_cells, float batch_inv)
{
    const int tid = threadIdx.x;
    const uint32_t sbase = (uint32_t)__cvta_generic_to_shared(smem);

    float acc = 0.0f;

    // prologue: prefetch first tile
    const int t0 = blockIdx.x;
    if (t0 < n_tiles)
        prefetch_tile(t0, 0, preds, truths, sbase, tid);
    cp_commit();

    int stage = 0;
    for (int t = t0; t < n_tiles; t += gridDim.x) {
        const int tn = t + gridDim.x;
        if (tn < n_tiles)
            prefetch_tile(tn, stage ^ 1, preds, truths, sbase, tid);
        cp_commit();
        cp_wait1();            // FIFO retirement -> tile t is resident
        __syncthreads();

        const float* P = smem + stage * STAGE_FLOATS + tid * CVALS;
        const float* T = P + TFLOATS;
        acc += cell_loss(P, T);

        __syncthreads();       // protect this stage before it is re-filled
        stage ^= 1;
    }

    // generic remainder (n_cells not a multiple of TILE) — block 0, direct loads
    const int rem_base = n_tiles * TILE;
    if (blockIdx.x == 0) {
        const int cell = rem_base + tid;
        if (cell < n_cells)
            acc += cell_loss(preds + (long long)cell * CVALS,
                             truths + (long long)cell * CVALS);
    }

    // block reduction -> one atomic per CTA
    #pragma unroll
    for (int off = 16; off > 0; off >>= 1)
        acc += __shfl_down_sync(0xFFFFFFFFu, acc, off);

    __shared__ float warp_sums[TILE / 32];
    const int warp = tid >> 5;
    const int lane = tid & 31;
    if (lane == 0) warp_sums[warp] = acc;
    __syncthreads();

    if (tid == 0) {
        float s = 0.0f;
        #pragma unroll
        for (int w = 0; w < TILE / 32; w++) s += warp_sums[w];
        atomicAdd(out, s * batch_inv);
    }
}

extern "C" void kernel_launch(void* const* d_in, const int* in_sizes, int n_in,
                              void* d_out, int out_size)
{
    const float* preds  = (const float*)d_in[0];
    const float* truths = (const float*)d_in[1];
    float* out = (float*)d_out;

    const int n_cells = in_sizes[0] / CVALS;     // 802816
    const int n_tiles = n_cells / TILE;          // 6272 (exact for this shape)

    cudaFuncSetAttribute(yolo_loss_kernel,
                         cudaFuncAttributeMaxDynamicSharedMemorySize, SMEM_BYTES);

    cudaMemsetAsync(d_out, 0, sizeof(float), 0);
    yolo_loss_kernel<<<NBLOCKS, TILE, SMEM_BYTES, 0>>>(preds, truths, out,
                                                       n_tiles, n_cells, BATCH_INV);
}